// round 5
// baseline (speedup 1.0000x reference)
#include <cuda_runtime.h>
#include <math.h>

#define BB  8
#define NN1 128
#define NN2 512
#define DD  128
#define MROWS (BB * (NN1 + NN2))   // 5120 combined rows
#define R1   (BB * NN1)            // 1024 graph-1 rows
#define LDH  256                   // hhA row stride: [h(128) | hA(128)]

// ---------------- static device scratch ----------------
__device__ float g_g   [MROWS * DD];
__device__ float g_hhA [MROWS * LDH];
__device__ float g_e2  [BB * NN2 * NN2];
__device__ float g_a2  [BB * NN2 * NN2];
__device__ float g_e1  [BB * NN1 * NN1];
__device__ float g_a1  [BB * NN1 * NN1];
__device__ float g_Wcat[3 * DD * LDH];
__device__ float g_bcat[3 * LDH];
__device__ float g_P1A [BB * NN1 * DD];
__device__ float g_P1B [BB * NN1 * DD];
__device__ float g_P2A [BB * NN2 * DD];
__device__ float g_P2B [BB * NN2 * DD];
__device__ float g_ZA  [BB * NN1 * NN2];
__device__ float g_ZB  [BB * NN1 * NN2];
__device__ float g_part[BB * NN1 * 4];

// ---------------- 128x64 NN GEMM body: C = A[M,K]@B[K,N] + bias ----------------
// 256 threads, 8x4 micro-tile, K multiple of 16.
__device__ __forceinline__ void gemm_nn2_body(const float* __restrict__ A, int lda,
                                              const float* __restrict__ B, int ldb,
                                              const float* __restrict__ bias,
                                              float* __restrict__ C, int ldc,
                                              int K, int m0, int n0) {
    __shared__ float As[16][132];
    __shared__ float Bs[16][68];
    int tid = threadIdx.x;
    int ar = tid >> 1, ac = (tid & 1) * 8;
    int br = tid >> 4, bc = (tid & 15) * 4;
    int tx = tid & 15, ty = tid >> 4;
    float acc[8][4] = {};
    for (int k0 = 0; k0 < K; k0 += 16) {
        float4 a0 = *(const float4*)&A[(long)(m0 + ar) * lda + k0 + ac];
        float4 a1 = *(const float4*)&A[(long)(m0 + ar) * lda + k0 + ac + 4];
        As[ac + 0][ar] = a0.x; As[ac + 1][ar] = a0.y;
        As[ac + 2][ar] = a0.z; As[ac + 3][ar] = a0.w;
        As[ac + 4][ar] = a1.x; As[ac + 5][ar] = a1.y;
        As[ac + 6][ar] = a1.z; As[ac + 7][ar] = a1.w;
        *(float4*)&Bs[br][bc] = *(const float4*)&B[(long)(k0 + br) * ldb + n0 + bc];
        __syncthreads();
        #pragma unroll
        for (int k = 0; k < 16; k++) {
            float4 av0 = *(float4*)&As[k][ty * 8];
            float4 av1 = *(float4*)&As[k][ty * 8 + 4];
            float4 bv  = *(float4*)&Bs[k][tx * 4];
            float am[8] = {av0.x, av0.y, av0.z, av0.w, av1.x, av1.y, av1.z, av1.w};
            float bn_[4] = {bv.x, bv.y, bv.z, bv.w};
            #pragma unroll
            for (int i = 0; i < 8; i++)
                #pragma unroll
                for (int j = 0; j < 4; j++)
                    acc[i][j] += am[i] * bn_[j];
        }
        __syncthreads();
    }
    #pragma unroll
    for (int i = 0; i < 8; i++) {
        int m = m0 + ty * 8 + i, n = n0 + tx * 4;
        float4 v;
        v.x = acc[i][0] + (bias ? bias[n + 0] : 0.f);
        v.y = acc[i][1] + (bias ? bias[n + 1] : 0.f);
        v.z = acc[i][2] + (bias ? bias[n + 2] : 0.f);
        v.w = acc[i][3] + (bias ? bias[n + 3] : 0.f);
        *(float4*)&C[(long)m * ldc + n] = v;
    }
}

// ---------------- 128x64 NT GEMM body: C = A[M,K]@B[N,K]^T ----------------
__device__ __forceinline__ void gemm_nt2_body(const float* __restrict__ A, int lda,
                                              const float* __restrict__ B, int ldb,
                                              float* __restrict__ C, int ldc,
                                              int K, int m0, int n0) {
    __shared__ float As[16][132];
    __shared__ float Bs[16][68];
    int tid = threadIdx.x;
    int ar = tid >> 1, ac = (tid & 1) * 8;
    int br = tid >> 2, bc = (tid & 3) * 4;
    int tx = tid & 15, ty = tid >> 4;
    float acc[8][4] = {};
    for (int k0 = 0; k0 < K; k0 += 16) {
        float4 a0 = *(const float4*)&A[(long)(m0 + ar) * lda + k0 + ac];
        float4 a1 = *(const float4*)&A[(long)(m0 + ar) * lda + k0 + ac + 4];
        As[ac + 0][ar] = a0.x; As[ac + 1][ar] = a0.y;
        As[ac + 2][ar] = a0.z; As[ac + 3][ar] = a0.w;
        As[ac + 4][ar] = a1.x; As[ac + 5][ar] = a1.y;
        As[ac + 6][ar] = a1.z; As[ac + 7][ar] = a1.w;
        float4 b4 = *(const float4*)&B[(long)(n0 + br) * ldb + k0 + bc];
        Bs[bc + 0][br] = b4.x; Bs[bc + 1][br] = b4.y;
        Bs[bc + 2][br] = b4.z; Bs[bc + 3][br] = b4.w;
        __syncthreads();
        #pragma unroll
        for (int k = 0; k < 16; k++) {
            float4 av0 = *(float4*)&As[k][ty * 8];
            float4 av1 = *(float4*)&As[k][ty * 8 + 4];
            float4 bv  = *(float4*)&Bs[k][tx * 4];
            float am[8] = {av0.x, av0.y, av0.z, av0.w, av1.x, av1.y, av1.z, av1.w};
            float bn_[4] = {bv.x, bv.y, bv.z, bv.w};
            #pragma unroll
            for (int i = 0; i < 8; i++)
                #pragma unroll
                for (int j = 0; j < 4; j++)
                    acc[i][j] += am[i] * bn_[j];
        }
        __syncthreads();
    }
    #pragma unroll
    for (int i = 0; i < 8; i++) {
        int m = m0 + ty * 8 + i, n = n0 + tx * 4;
        float4 v = {acc[i][0], acc[i][1], acc[i][2], acc[i][3]};
        *(float4*)&C[(long)m * ldc + n] = v;
    }
}

// Wcat[:,0:128] = W
__global__ void k_wcat_copy(const float* __restrict__ W, float* __restrict__ Wcat) {
    int idx = blockIdx.x * 256 + threadIdx.x;     // 3*128*128
    int l = idx / (DD * DD), r = idx % (DD * DD);
    int k = r / DD, n = r % DD;
    Wcat[(long)l * DD * LDH + (long)k * LDH + n] = W[idx];
}

// Wcat[:,128:256] = W @ A
__global__ void k_wcat_wa(const float* __restrict__ W, const float* __restrict__ A,
                          float* __restrict__ Wcat) {
    int l = blockIdx.z;
    gemm_nn2_body(W + (long)l * DD * DD, DD, A + (long)l * DD * DD, DD, nullptr,
                  Wcat + (long)l * DD * LDH + 128, LDH, DD, 0, blockIdx.x * 64);
}

// bcat = [b, b@A]
__global__ void k_bcat(const float* __restrict__ b, const float* __restrict__ A,
                       float* __restrict__ bcat) {
    int l = blockIdx.x, n = threadIdx.x;
    float acc = 0.f;
    #pragma unroll 8
    for (int k = 0; k < DD; k++)
        acc += b[l * DD + k] * A[((long)l * DD + k) * DD + n];
    bcat[l * LDH + n] = b[l * DD + n];
    bcat[l * LDH + 128 + n] = acc;
}

// embedding for both graphs
__global__ void k_embed_both(const float* __restrict__ X1, const float* __restrict__ X2,
                             const float* __restrict__ W, float* __restrict__ Y) {
    int bn = blockIdx.x;
    const float* src = (bn < R1) ? X1 + (size_t)bn * 54
                                 : X2 + (size_t)(bn - R1) * 54;
    __shared__ float xs[54];
    if (threadIdx.x < 54) xs[threadIdx.x] = src[threadIdx.x];
    __syncthreads();
    int d = threadIdx.x;
    float acc = 0.f;
    #pragma unroll
    for (int l = 0; l < 54; l++) acc += xs[l] * W[l * DD + d];
    Y[(size_t)bn * DD + d] = acc;
}

// hhA = g @ Wcat + bcat   (M=5120, N=256, K=128)
__global__ void k_dual2(const float* __restrict__ g, const float* __restrict__ Wcat,
                        const float* __restrict__ bcat, float* __restrict__ hhA) {
    gemm_nn2_body(g, DD, Wcat, LDH, bcat, hhA, LDH, DD,
                  blockIdx.y * 128, blockIdx.x * 64);
}

// e = hA @ h^T per batch; both graphs. z<8: graph2; z>=8: graph1.
__global__ void k_nt_both2(const float* __restrict__ hhA, float* __restrict__ e2,
                           float* __restrict__ e1) {
    int z = blockIdx.z;
    if (z < 8) {
        const float* base = hhA + ((long)R1 + (long)z * NN2) * LDH;
        gemm_nt2_body(base + 128, LDH, base, LDH, e2 + (long)z * NN2 * NN2, NN2,
                      DD, blockIdx.y * 128, blockIdx.x * 64);
    } else {
        if (blockIdx.y >= 1 || blockIdx.x >= 2) return;
        const float* base = hhA + (long)(z - 8) * NN1 * LDH;
        gemm_nt2_body(base + 128, LDH, base, LDH, e1 + (long)(z - 8) * NN1 * NN1, NN1,
                      DD, 0, blockIdx.x * 64);
    }
}

// fused symmetrize + mask + column softmax (axis=1), both graphs
__global__ void k_softmax_both(const float* __restrict__ e2, const float* __restrict__ adj2,
                               float* __restrict__ a2, const float* __restrict__ e1,
                               const float* __restrict__ adj1, float* __restrict__ a1) {
    extern __shared__ float Ls[];   // N*33 floats
    __shared__ float Ts[32][33];
    __shared__ float red[8][33];
    int z = blockIdx.y;
    int N; const float* Eb; const float* Ab; float* Ob;
    if (z < 8) {
        N = NN2;
        Eb = e2 + (long)z * NN2 * NN2; Ab = adj2 + (long)z * NN2 * NN2;
        Ob = a2 + (long)z * NN2 * NN2;
    } else {
        if (blockIdx.x >= NN1 / 32) return;
        N = NN1;
        Eb = e1 + (long)(z - 8) * NN1 * NN1; Ab = adj1 + (long)(z - 8) * NN1 * NN1;
        Ob = a1 + (long)(z - 8) * NN1 * NN1;
    }
    int k0 = blockIdx.x * 32;
    int tx = threadIdx.x, ty = threadIdx.y;
    for (int i0 = 0; i0 < N; i0 += 32) {
        for (int r = ty; r < 32; r += 8)
            Ts[r][tx] = Eb[(size_t)(k0 + r) * N + i0 + tx];
        __syncthreads();
        for (int r = ty; r < 32; r += 8) {
            float d = Eb[(size_t)(i0 + r) * N + k0 + tx];
            float a = Ab[(size_t)(i0 + r) * N + k0 + tx];
            Ls[(i0 + r) * 33 + tx] = (a > 0.f) ? (d + Ts[tx][r]) : -9e15f;
        }
        __syncthreads();
    }
    float m = -3.4e38f;
    for (int i = ty; i < N; i += 8) m = fmaxf(m, Ls[i * 33 + tx]);
    red[ty][tx] = m;
    __syncthreads();
    if (ty == 0) {
        float mm = red[0][tx];
        #pragma unroll
        for (int y = 1; y < 8; y++) mm = fmaxf(mm, red[y][tx]);
        red[0][tx] = mm;
    }
    __syncthreads();
    m = red[0][tx];
    __syncthreads();
    float s = 0.f;
    for (int i = ty; i < N; i += 8) {
        float e = __expf(Ls[i * 33 + tx] - m);
        Ls[i * 33 + tx] = e;
        s += e;
    }
    red[ty][tx] = s;
    __syncthreads();
    if (ty == 0) {
        float ss = 0.f;
        #pragma unroll
        for (int y = 0; y < 8; y++) ss += red[y][tx];
        red[0][tx] = ss;
    }
    __syncthreads();
    float inv = 1.f / red[0][tx];
    for (int i = ty; i < N; i += 8)
        Ob[(size_t)i * N + k0 + tx] = Ls[i * 33 + tx] * inv;
}

// fused: hp = relu(att@h); c = sigmoid(g.gW1 + hp.gW2 + gb); g = c*g + (1-c)*hp
// tile 64 rows x 128 cols, 4x8 micro-tile.
__global__ void k_relugate2(const float* __restrict__ a2, const float* __restrict__ a1,
                            const float* __restrict__ hhA, float* __restrict__ g,
                            const float* __restrict__ gW, const float* __restrict__ gb) {
    int z = blockIdx.z;
    int M, K; const float* att; const float* Hb; float* G;
    if (z < 8) {
        M = NN2; K = NN2;
        att = a2 + (long)z * NN2 * NN2;
        Hb = hhA + ((long)R1 + (long)z * NN2) * LDH;
        G  = g + ((long)R1 + (long)z * NN2) * DD;
    } else {
        M = NN1; K = NN1;
        att = a1 + (long)(z - 8) * NN1 * NN1;
        Hb = hhA + (long)(z - 8) * NN1 * LDH;
        G  = g + (long)(z - 8) * NN1 * DD;
    }
    int m0 = blockIdx.y * 64;
    if (m0 >= M) return;
    __shared__ float As[16][68];    // [k][i] 64 rows
    __shared__ float Bs[16][132];   // [k][j] 128 cols
    __shared__ float gw1[DD], gw2[DD];
    __shared__ float redH[64][17], redX[64][17];
    __shared__ float csm[64];
    int tid = threadIdx.x;
    int jg = tid & 15, ig = tid >> 4;
    if (tid < DD) { gw1[tid] = gW[tid]; gw2[tid] = gW[DD + tid]; }
    int ar = tid >> 2, ac = (tid & 3) * 4;
    int br = tid >> 4, bc = (tid & 15) * 8;
    float acc[4][8] = {};
    for (int k0 = 0; k0 < K; k0 += 16) {
        float4 a4 = *(const float4*)&att[(long)(m0 + ar) * K + k0 + ac];
        As[ac + 0][ar] = a4.x; As[ac + 1][ar] = a4.y;
        As[ac + 2][ar] = a4.z; As[ac + 3][ar] = a4.w;
        *(float4*)&Bs[br][bc]     = *(const float4*)&Hb[(long)(k0 + br) * LDH + bc];
        *(float4*)&Bs[br][bc + 4] = *(const float4*)&Hb[(long)(k0 + br) * LDH + bc + 4];
        __syncthreads();
        #pragma unroll
        for (int k = 0; k < 16; k++) {
            float4 av = *(float4*)&As[k][ig * 4];
            float4 b0 = *(float4*)&Bs[k][jg * 8];
            float4 b1 = *(float4*)&Bs[k][jg * 8 + 4];
            float am[4] = {av.x, av.y, av.z, av.w};
            float bn_[8] = {b0.x, b0.y, b0.z, b0.w, b1.x, b1.y, b1.z, b1.w};
            #pragma unroll
            for (int i = 0; i < 4; i++)
                #pragma unroll
                for (int j = 0; j < 8; j++)
                    acc[i][j] += am[i] * bn_[j];
        }
        __syncthreads();
    }
    float xv[4][8];
    #pragma unroll
    for (int i = 0; i < 4; i++) {
        int m = m0 + ig * 4 + i;
        float4 x0 = *(const float4*)&G[(long)m * DD + jg * 8];
        float4 x1 = *(const float4*)&G[(long)m * DD + jg * 8 + 4];
        xv[i][0] = x0.x; xv[i][1] = x0.y; xv[i][2] = x0.z; xv[i][3] = x0.w;
        xv[i][4] = x1.x; xv[i][5] = x1.y; xv[i][6] = x1.z; xv[i][7] = x1.w;
    }
    #pragma unroll
    for (int i = 0; i < 4; i++) {
        float sh = 0.f, sx = 0.f;
        #pragma unroll
        for (int j = 0; j < 8; j++) {
            acc[i][j] = fmaxf(acc[i][j], 0.f);
            sh += acc[i][j] * gw2[jg * 8 + j];
            sx += xv[i][j] * gw1[jg * 8 + j];
        }
        redH[ig * 4 + i][jg] = sh;
        redX[ig * 4 + i][jg] = sx;
    }
    __syncthreads();
    if (tid < 64) {
        float s = 0.f;
        #pragma unroll
        for (int t = 0; t < 16; t++) s += redH[tid][t] + redX[tid][t];
        s += gb[0];
        csm[tid] = 1.f / (1.f + __expf(-s));
    }
    __syncthreads();
    #pragma unroll
    for (int i = 0; i < 4; i++) {
        int m = m0 + ig * 4 + i;
        float c = csm[ig * 4 + i];
        float4 v0, v1;
        v0.x = c * xv[i][0] + (1.f - c) * acc[i][0];
        v0.y = c * xv[i][1] + (1.f - c) * acc[i][1];
        v0.z = c * xv[i][2] + (1.f - c) * acc[i][2];
        v0.w = c * xv[i][3] + (1.f - c) * acc[i][3];
        v1.x = c * xv[i][4] + (1.f - c) * acc[i][4];
        v1.y = c * xv[i][5] + (1.f - c) * acc[i][5];
        v1.z = c * xv[i][6] + (1.f - c) * acc[i][6];
        v1.w = c * xv[i][7] + (1.f - c) * acc[i][7];
        *(float4*)&G[(long)m * DD + jg * 8]     = v0;
        *(float4*)&G[(long)m * DD + jg * 8 + 4] = v1;
    }
}

// all 4 pair projections in one launch (z: 0=p1a 1=p1b 2=p2a 3=p2b)
__global__ void k_proj2(const float* __restrict__ g,
                        const float* __restrict__ WA1, const float* __restrict__ bA1,
                        const float* __restrict__ WB1, const float* __restrict__ bB1,
                        float* __restrict__ p1a, float* __restrict__ p1b,
                        float* __restrict__ p2a, float* __restrict__ p2b) {
    int z = blockIdx.z;
    const float* A; const float* B; const float* bias; float* C; int mt;
    switch (z) {
        case 0: A = g;                 B = WA1;           bias = bA1;   C = p1a; mt = R1 / 128; break;
        case 1: A = g;                 B = WB1;           bias = bB1;   C = p1b; mt = R1 / 128; break;
        case 2: A = g + (long)R1 * DD; B = WA1 + DD * DD; bias = nullptr; C = p2a; mt = (BB * NN2) / 128; break;
        default:A = g + (long)R1 * DD; B = WB1 + DD * DD; bias = nullptr; C = p2b; mt = (BB * NN2) / 128; break;
    }
    if ((int)blockIdx.y >= mt) return;
    gemm_nn2_body(A, DD, B, DD, bias, C, DD, DD, blockIdx.y * 128, blockIdx.x * 64);
}

// Z[b,i,j] = act( b2 + sum_h relu(P1[i,h]+P2[j,h]) * w2[h] ), 32x32 tiles
__global__ void k_zmat(const float* __restrict__ p1a, const float* __restrict__ p1b,
                       const float* __restrict__ p2a, const float* __restrict__ p2b,
                       const float* __restrict__ w2A, const float* __restrict__ w2B,
                       const float* __restrict__ b2A, const float* __restrict__ b2B,
                       float* __restrict__ ZA, float* __restrict__ ZB) {
    __shared__ float P1s[DD][33];
    __shared__ float P2s[DD][33];
    __shared__ float w2s[DD];
    int z = blockIdx.z;
    int b = z >> 1, mlp = z & 1;
    const float* P1 = (mlp ? p1b : p1a) + (long)b * NN1 * DD;
    const float* P2 = (mlp ? p2b : p2a) + (long)b * NN2 * DD;
    const float* w2 = mlp ? w2B : w2A;
    float b2 = mlp ? b2B[0] : b2A[0];
    float* Z = (mlp ? ZB : ZA) + (long)b * NN1 * NN2;
    int i0 = blockIdx.y * 32, j0 = blockIdx.x * 32;
    int tid = threadIdx.x;
    if (tid < DD) w2s[tid] = w2[tid];
    {
        int row = tid >> 3, cb = (tid & 7) * 16;
        #pragma unroll
        for (int q = 0; q < 4; q++) {
            float4 v1 = *(const float4*)&P1[(long)(i0 + row) * DD + cb + q * 4];
            float4 v2 = *(const float4*)&P2[(long)(j0 + row) * DD + cb + q * 4];
            P1s[cb + q * 4 + 0][row] = v1.x; P1s[cb + q * 4 + 1][row] = v1.y;
            P1s[cb + q * 4 + 2][row] = v1.z; P1s[cb + q * 4 + 3][row] = v1.w;
            P2s[cb + q * 4 + 0][row] = v2.x; P2s[cb + q * 4 + 1][row] = v2.y;
            P2s[cb + q * 4 + 2][row] = v2.z; P2s[cb + q * 4 + 3][row] = v2.w;
        }
    }
    __syncthreads();
    int tx = tid & 15, ty = tid >> 4;
    float a00 = 0.f, a01 = 0.f, a10 = 0.f, a11 = 0.f;
    #pragma unroll 4
    for (int k = 0; k < DD; k++) {
        float w = w2s[k];
        float p0 = P1s[k][ty], p1 = P1s[k][ty + 16];
        float q0 = P2s[k][tx], q1 = P2s[k][tx + 16];
        a00 += fmaxf(p0 + q0, 0.f) * w;
        a01 += fmaxf(p0 + q1, 0.f) * w;
        a10 += fmaxf(p1 + q0, 0.f) * w;
        a11 += fmaxf(p1 + q1, 0.f) * w;
    }
    a00 += b2; a01 += b2; a10 += b2; a11 += b2;
    if (mlp == 0) {
        a00 = 1.f / (1.f + __expf(-a00)); a01 = 1.f / (1.f + __expf(-a01));
        a10 = 1.f / (1.f + __expf(-a10)); a11 = 1.f / (1.f + __expf(-a11));
    } else {
        a00 = tanhf(a00) * 0.2f; a01 = tanhf(a01) * 0.2f;
        a10 = tanhf(a10) * 0.2f; a11 = tanhf(a11) * 0.2f;
    }
    Z[(long)(i0 + ty) * NN2 + j0 + tx]           = a00;
    Z[(long)(i0 + ty) * NN2 + j0 + tx + 16]      = a01;
    Z[(long)(i0 + ty + 16) * NN2 + j0 + tx]      = a10;
    Z[(long)(i0 + ty + 16) * NN2 + j0 + tx + 16] = a11;
}

// elementwise physics + per-(b,i) reduction
__global__ void k_phys(const float* __restrict__ ZA, const float* __restrict__ ZB,
                       const float* __restrict__ pos1, const float* __restrict__ pos2,
                       const float* __restrict__ r1, const float* __restrict__ r2,
                       const float* __restrict__ nm1, const float* __restrict__ nm2,
                       const float* __restrict__ A_int, float* __restrict__ part) {
    int b = blockIdx.x >> 7, i = blockIdx.x & 127;
    int t = threadIdx.x;
    float px = pos1[(b * NN1 + i) * 3 + 0];
    float py = pos1[(b * NN1 + i) * 3 + 1];
    float pz = pos1[(b * NN1 + i) * 3 + 2];
    float rr1 = r1[b * NN1 + i];
    float m1  = nm1[b * NN1 + i];
    size_t zbase = (size_t)b * NN1 * NN2 + (size_t)i * NN2;
    size_t abase = (size_t)b * 8 * NN1 * NN2 + (size_t)i * NN2;
    const size_t chw = (size_t)NN1 * NN2;
    float s0 = 0.f, s1 = 0.f, s2 = 0.f, s3 = 0.f;
    for (int j = t; j < NN2; j += 128) {
        float Aw = ZA[zbase + j];
        float Bw = ZB[zbase + j];
        float dx = px - pos2[(b * NN2 + j) * 3 + 0];
        float dy = py - pos2[(b * NN2 + j) * 3 + 1];
        float dz = pz - pos2[(b * NN2 + j) * 3 + 2];
        float dm = sqrtf(dx * dx + dy * dy + dz * dz + 1e-10f);
        if (dm < 0.5f) dm = 1e10f;
        float dm0 = rr1 + r2[b * NN2 + j] + Bw;
        float dm0s = (dm0 < 1e-4f) ? 1.f : dm0;
        float rq = dm0s / dm;
        float rq2 = rq * rq;
        float r6 = rq2 * rq2 * rq2;
        float evdw = fminf(r6 * r6 - 2.f * r6, 100.f);
        float Aamp = Aw * (0.0356f - 0.0178f) + 0.0178f;
        s0 += Aamp * evdw * m1 * nm2[b * NN2 + j];
        float dmd = dm - dm0;
        float a1 = A_int[abase + 1 * chw + j];
        float a7 = A_int[abase + 7 * chw + j];
        float a6 = A_int[abase + 6 * chw + j];
        s1 += fminf(fmaxf(dmd * a1 * (-1.f / 0.7f), 0.f), 1.f);
        s2 += fminf(fmaxf(dmd * a7 * (-1.f / 0.7f), 0.f), 1.f);
        s3 += fminf(fmaxf((1.5f - dmd) * a6, 0.f), 1.f);
    }
    #pragma unroll
    for (int o = 16; o > 0; o >>= 1) {
        s0 += __shfl_down_sync(0xffffffffu, s0, o);
        s1 += __shfl_down_sync(0xffffffffu, s1, o);
        s2 += __shfl_down_sync(0xffffffffu, s2, o);
        s3 += __shfl_down_sync(0xffffffffu, s3, o);
    }
    __shared__ float acc[4][4];
    int lane = t & 31, w = t >> 5;
    if (lane == 0) { acc[w][0] = s0; acc[w][1] = s1; acc[w][2] = s2; acc[w][3] = s3; }
    __syncthreads();
    if (t < 4)
        part[((size_t)b * NN1 + i) * 4 + t] = acc[0][t] + acc[1][t] + acc[2][t] + acc[3][t];
}

__global__ void k_final(const float* __restrict__ part, const float* __restrict__ rotor,
                        const float* __restrict__ duff, const float* __restrict__ hbc,
                        const float* __restrict__ hyc, const float* __restrict__ vdc,
                        const float* __restrict__ rtc, float* __restrict__ out) {
    int b = blockIdx.x, t = threadIdx.x;
    size_t base = ((size_t)b * NN1 + t) * 4;
    float v0 = part[base + 0], v1 = part[base + 1], v2 = part[base + 2], v3 = part[base + 3];
    #pragma unroll
    for (int o = 16; o > 0; o >>= 1) {
        v0 += __shfl_down_sync(0xffffffffu, v0, o);
        v1 += __shfl_down_sync(0xffffffffu, v1, o);
        v2 += __shfl_down_sync(0xffffffffu, v2, o);
        v3 += __shfl_down_sync(0xffffffffu, v3, o);
    }
    __shared__ float red[4][4];
    if ((t & 31) == 0) {
        int w = t >> 5;
        red[w][0] = v0; red[w][1] = v1; red[w][2] = v2; red[w][3] = v3;
    }
    __syncthreads();
    if (t == 0) {
        float s0 = red[0][0] + red[1][0] + red[2][0] + red[3][0];
        float s1 = red[0][1] + red[1][1] + red[2][1] + red[3][1];
        float s2 = red[0][2] + red[1][2] + red[2][2] + red[3][2];
        float s3 = red[0][3] + red[1][3] + red[2][3] + red[3][3];
        float hb = -hbc[0] * hbc[0];
        float hy = -hyc[0] * hyc[0];
        float inv = 1.f / (1.f + rtc[0] * rtc[0] * rotor[b]);
        out[b * 5 + 0] = s0 * inv;
        out[b * 5 + 1] = s1 * hb * inv;
        out[b * 5 + 2] = s2 * hb * inv;
        out[b * 5 + 3] = s3 * hy * inv;
        out[b * 5 + 4] = duff[b] * vdc[0] * vdc[0] * inv;
    }
}

// ---------------- host side ----------------
extern "C" void kernel_launch(void* const* d_in, const int* in_sizes, int n_in,
                              void* d_out, int out_size) {
    (void)in_sizes; (void)n_in; (void)out_size;
    const float* h1      = (const float*)d_in[0];
    const float* adj1    = (const float*)d_in[1];
    const float* h2      = (const float*)d_in[2];
    const float* adj2    = (const float*)d_in[3];
    const float* A_int   = (const float*)d_in[4];
    const float* pos1    = (const float*)d_in[5];
    const float* pos2    = (const float*)d_in[6];
    const float* rotor   = (const float*)d_in[7];
    const float* vdw_r1  = (const float*)d_in[8];
    const float* vdw_r2  = (const float*)d_in[9];
    const float* duff    = (const float*)d_in[10];
    const float* nm1     = (const float*)d_in[11];
    const float* nm2     = (const float*)d_in[12];
    const float* node_W  = (const float*)d_in[13];
    const float* gat_W   = (const float*)d_in[14];
    const float* gat_b   = (const float*)d_in[15];
    const float* gat_A   = (const float*)d_in[16];
    const float* gate_W  = (const float*)d_in[17];
    const float* gate_b  = (const float*)d_in[18];
    const float* vdwA_W1 = (const float*)d_in[19];
    const float* vdwA_b1 = (const float*)d_in[20];
    const float* vdwA_W2 = (const float*)d_in[21];
    const float* vdwA_b2 = (const float*)d_in[22];
    const float* vdwB_W1 = (const float*)d_in[23];
    const float* vdwB_b1 = (const float*)d_in[24];
    const float* vdwB_W2 = (const float*)d_in[25];
    const float* vdwB_b2 = (const float*)d_in[26];
    const float* hbond   = (const float*)d_in[27];
    const float* hydro   = (const float*)d_in[28];
    const float* vdwc    = (const float*)d_in[29];
    const float* rotc    = (const float*)d_in[30];
    float* out = (float*)d_out;

    float *gp, *hhAp, *e2p, *a2p, *e1p, *a1p, *wcp, *bcp;
    float *p1a, *p1b, *p2a, *p2b, *zap, *zbp, *partp;
    cudaGetSymbolAddress((void**)&gp,   g_g);
    cudaGetSymbolAddress((void**)&hhAp, g_hhA);
    cudaGetSymbolAddress((void**)&e2p,  g_e2);
    cudaGetSymbolAddress((void**)&a2p,  g_a2);
    cudaGetSymbolAddress((void**)&e1p,  g_e1);
    cudaGetSymbolAddress((void**)&a1p,  g_a1);
    cudaGetSymbolAddress((void**)&wcp,  g_Wcat);
    cudaGetSymbolAddress((void**)&bcp,  g_bcat);
    cudaGetSymbolAddress((void**)&p1a,  g_P1A);
    cudaGetSymbolAddress((void**)&p1b,  g_P1B);
    cudaGetSymbolAddress((void**)&p2a,  g_P2A);
    cudaGetSymbolAddress((void**)&p2b,  g_P2B);
    cudaGetSymbolAddress((void**)&zap,  g_ZA);
    cudaGetSymbolAddress((void**)&zbp,  g_ZB);
    cudaGetSymbolAddress((void**)&partp, g_part);

    (void)cudaFuncSetAttribute(k_softmax_both,
                               cudaFuncAttributeMaxDynamicSharedMemorySize,
                               NN2 * 33 * 4);

    // precompute Wcat/bcat; embedding
    k_wcat_copy<<<3 * DD * DD / 256, 256>>>(gat_W, wcp);
    k_bcat<<<3, DD>>>(gat_b, gat_A, bcp);
    k_wcat_wa<<<dim3(2, 1, 3), 256>>>(gat_W, gat_A, wcp);
    k_embed_both<<<MROWS, DD>>>(h1, h2, node_W, gp);

    for (int l = 0; l < 3; l++) {
        const float* Wc = wcp + (size_t)l * DD * LDH;
        const float* bc = bcp + (size_t)l * LDH;
        const float* gW = gate_W + (size_t)l * 2 * DD;
        const float* gb = gate_b + l;
        k_dual2<<<dim3(4, MROWS / 128, 1), 256>>>(gp, Wc, bc, hhAp);
        k_nt_both2<<<dim3(8, 4, 16), 256>>>(hhAp, e2p, e1p);
        k_softmax_both<<<dim3(16, 16), dim3(32, 8), NN2 * 33 * 4>>>(e2p, adj2, a2p,
                                                                    e1p, adj1, a1p);
        k_relugate2<<<dim3(1, 8, 16), 256>>>(a2p, a1p, hhAp, gp, gW, gb);
    }

    // pair projections (one launch)
    k_proj2<<<dim3(2, 32, 4), 256>>>(gp, vdwA_W1, vdwA_b1, vdwB_W1, vdwB_b1,
                                     p1a, p1b, p2a, p2b);
    // pair bilinear-relu MLP matrices
    k_zmat<<<dim3(16, 4, 16), 256>>>(p1a, p1b, p2a, p2b, vdwA_W2, vdwB_W2,
                                     vdwA_b2, vdwB_b2, zap, zbp);
    // physics + reductions
    k_phys<<<BB * NN1, 128>>>(zap, zbp, pos1, pos2, vdw_r1, vdw_r2, nm1, nm2,
                              A_int, partp);
    k_final<<<BB, 128>>>(partp, rotor, duff, hbond, hydro, vdwc, rotc, out);
}